// round 16
// baseline (speedup 1.0000x reference)
#include <cuda_runtime.h>
#include <cuda_bf16.h>
#include <cuda_fp16.h>

// SparseSelfAttention via portable mma.sync, FA2-style. R16 probe:
// QK uses fp16 operands — main term f16xf16->f32acc, correction terms
// (qh*kl + ql*kh) share an f16-accum chain (tests whether f16-acc HMMA is 2x).
// PV unchanged (bf16 3-term, f32 acc). Structure otherwise = R14.

#define BSZ    2
#define HEADS  16
#define SEQ    4096
#define DIM    64
#define SHIFT2 28.853900817779268f   // 20 * log2(e)
#define LOG2E  1.4426950408889634f
#define NTHREADS 128

#define RS 144                  // smem row stride in BYTES
#define TILE (64 * RS)          // 9216 B per 64-row 16-bit tile
#define REG  (4 * TILE)         // KH,KL,VH,VL region = 36864 B

#define SM_MASK  (3 * REG)                 // 110592
#define SM_TOTAL (SM_MASK + 6 * 64 * 4)    // 112128 B -> 2 CTAs/SM

typedef unsigned int u32;

// pre-pass scratch: [bh][KH,KL,VH,VL][256 g][64 d] 16-bit = 4 MB
// K planes hold fp16 (pre-scaled by log2e), V planes hold bf16.
__device__ __nv_bfloat16 g_split[32][4][256][64];

static __device__ __forceinline__ u32 smem_u32(const void* p) {
    u32 a;
    asm("{ .reg .u64 t; cvta.to.shared.u64 t, %1; cvt.u32.u64 %0, t; }" : "=r"(a) : "l"(p));
    return a;
}
// bf16x2 {lo=a, hi=b}
static __device__ __forceinline__ u32 pkbf(float a, float b) {
    u32 r;
    asm("cvt.rn.bf16x2.f32 %0, %1, %2;" : "=r"(r) : "f"(b), "f"(a));
    return r;
}
// f16x2 {lo=a, hi=b}
static __device__ __forceinline__ u32 pkhf(float a, float b) {
    u32 r;
    asm("cvt.rn.f16x2.f32 %0, %1, %2;" : "=r"(r) : "f"(b), "f"(a));
    return r;
}
static __device__ __forceinline__ float lo_f(u32 h) { return __uint_as_float(h << 16); }
static __device__ __forceinline__ float hi_f(u32 h) { return __uint_as_float(h & 0xFFFF0000u); }
static __device__ __forceinline__ float2 h2f2(u32 p) {
    float lo, hi;
    asm("{ .reg .f16 a, b; mov.b32 {a, b}, %2; cvt.f32.f16 %0, a; cvt.f32.f16 %1, b; }"
        : "=f"(lo), "=f"(hi) : "r"(p));
    return make_float2(lo, hi);
}
// fp16 hi/lo split of a float pair
static __device__ __forceinline__ void split16(float a, float b, u32& h, u32& l) {
    h = pkhf(a, b);
    float2 hf = h2f2(h);
    l = pkhf(a - hf.x, b - hf.y);
}
static __device__ __forceinline__ float ex2(float x) {
    float y;
    asm("ex2.approx.f32 %0, %1;" : "=f"(y) : "f"(x));
    return y;
}
static __device__ __forceinline__ void ldsm4(u32* r, u32 a) {
    asm volatile("ldmatrix.sync.aligned.m8n8.x4.shared.b16 {%0,%1,%2,%3}, [%4];"
                 : "=r"(r[0]), "=r"(r[1]), "=r"(r[2]), "=r"(r[3]) : "r"(a));
}
static __device__ __forceinline__ void ldsm4t(u32* r, u32 a) {
    asm volatile("ldmatrix.sync.aligned.m8n8.x4.trans.shared.b16 {%0,%1,%2,%3}, [%4];"
                 : "=r"(r[0]), "=r"(r[1]), "=r"(r[2]), "=r"(r[3]) : "r"(a));
}
// bf16 inputs, f32 accum
static __device__ __forceinline__ void mma_bf(float* c, const u32* a, u32 b0, u32 b1) {
    asm volatile(
        "mma.sync.aligned.m16n8k16.row.col.f32.bf16.bf16.f32 "
        "{%0,%1,%2,%3}, {%4,%5,%6,%7}, {%8,%9}, {%0,%1,%2,%3};"
        : "+f"(c[0]), "+f"(c[1]), "+f"(c[2]), "+f"(c[3])
        : "r"(a[0]), "r"(a[1]), "r"(a[2]), "r"(a[3]), "r"(b0), "r"(b1));
}
// fp16 inputs, f32 accum
static __device__ __forceinline__ void mma_hf32(float* c, const u32* a, u32 b0, u32 b1) {
    asm volatile(
        "mma.sync.aligned.m16n8k16.row.col.f32.f16.f16.f32 "
        "{%0,%1,%2,%3}, {%4,%5,%6,%7}, {%8,%9}, {%0,%1,%2,%3};"
        : "+f"(c[0]), "+f"(c[1]), "+f"(c[2]), "+f"(c[3])
        : "r"(a[0]), "r"(a[1]), "r"(a[2]), "r"(a[3]), "r"(b0), "r"(b1));
}
// fp16 inputs, f16 accum (the probe)
static __device__ __forceinline__ void mma_hf16(u32* c, const u32* a, u32 b0, u32 b1) {
    asm volatile(
        "mma.sync.aligned.m16n8k16.row.col.f16.f16.f16.f16 "
        "{%0,%1}, {%2,%3,%4,%5}, {%6,%7}, {%0,%1};"
        : "+r"(c[0]), "+r"(c[1])
        : "r"(a[0]), "r"(a[1]), "r"(a[2]), "r"(a[3]), "r"(b0), "r"(b1));
}
static __device__ __forceinline__ void cpasync16(u32 dst, const void* src) {
    asm volatile("cp.async.cg.shared.global [%0], [%1], 16;" :: "r"(dst), "l"(src));
}
#define CP_COMMIT() asm volatile("cp.async.commit_group;" ::: "memory")
#define CP_WAIT(n)  asm volatile("cp.async.wait_group %0;" :: "n"(n) : "memory")

static __device__ __forceinline__ int gpos(int g) {
    int blk = g >> 2, off = g & 3;
    return blk * 64 + (off == 0 ? 0 : 60 + off);
}

// ========== pre-pass: gather + split global K (fp16, x log2e) / V (bf16) ==========
__global__ __launch_bounds__(256)
void prepass_kernel(const float* __restrict__ K, const float* __restrict__ V)
{
    const int bh  = blockIdx.y;
    const int idx = threadIdx.x + blockIdx.x * 256;    // 0..4095
    const size_t bh_off = (size_t)bh * SEQ * DIM;
    uint2* out = (uint2*)g_split;

    int g = idx >> 4, d4 = idx & 15;
    int pos = gpos(g);

    float4 kf = *(const float4*)(K + bh_off + (size_t)pos * DIM + d4 * 4);
    kf.x *= LOG2E; kf.y *= LOG2E; kf.z *= LOG2E; kf.w *= LOG2E;
    u32 h01, l01, h23, l23;
    split16(kf.x, kf.y, h01, l01);
    split16(kf.z, kf.w, h23, l23);
    out[(bh * 4 + 0) * 4096 + g * 16 + d4] = make_uint2(h01, h23);
    out[(bh * 4 + 1) * 4096 + g * 16 + d4] = make_uint2(l01, l23);

    float4 vf = *(const float4*)(V + bh_off + (size_t)pos * DIM + d4 * 4);
    u32 vh01 = pkbf(vf.x, vf.y), vh23 = pkbf(vf.z, vf.w);
    u32 vl01 = pkbf(vf.x - lo_f(vh01), vf.y - hi_f(vh01));
    u32 vl23 = pkbf(vf.z - lo_f(vh23), vf.w - hi_f(vh23));
    out[(bh * 4 + 2) * 4096 + g * 16 + d4] = make_uint2(vh01, vh23);
    out[(bh * 4 + 3) * 4096 + g * 16 + d4] = make_uint2(vl01, vl23);
}

// ================= main kernel =================
extern __shared__ char smc[];

__global__ __launch_bounds__(NTHREADS, 2)
void sparse_attn_mma(const float* __restrict__ Q,
                     const float* __restrict__ K,
                     const float* __restrict__ V,
                     const float* __restrict__ Mask,
                     float* __restrict__ Out)
{
    const int qp = blockIdx.x;
    const int h  = blockIdx.y;
    const int b  = blockIdx.z;
    const int bh = b * HEADS + h;
    const size_t bh_off = (size_t)bh * SEQ * DIM;
    const size_t q_off  = bh_off + (size_t)qp * 128 * DIM;

    const int tid  = threadIdx.x;
    const int L    = tid & 31;
    const int warp = tid >> 5;
    const int qw   = warp * 32;

    const u32 smb = smem_u32(smc);
    const u32 R0 = smb, R1 = smb + REG, R2 = smb + 2 * REG;
    float* s_mask = (float*)(smc + SM_MASK);
    const u32 QHs = R2;
    const u32 QLs = R2 + 2 * TILE;

    // ---- prologue: Q (fp16 split) -> R2, local K (fp16) / V (bf16) -> R0/R1 ----
    #pragma unroll
    for (int i = 0; i < 16; i++) {
        int idx = tid + i * NTHREADS;
        int row = idx >> 4, d4 = idx & 15;
        u32 lreg = (row < 64) ? R0 : R1;
        int lrow = row & 63;

        float4 f = *(const float4*)(Q + q_off + (size_t)row * DIM + d4 * 4);
        u32 h01, l01, h23, l23;
        split16(f.x, f.y, h01, l01);
        split16(f.z, f.w, h23, l23);
        *(uint2*)(smc + (QHs - smb) + row * RS + d4 * 8) = make_uint2(h01, h23);
        *(uint2*)(smc + (QLs - smb) + row * RS + d4 * 8) = make_uint2(l01, l23);

        int pos = qp * 128 + row;
        float4 kf = *(const float4*)(K + bh_off + (size_t)pos * DIM + d4 * 4);
        kf.x *= LOG2E; kf.y *= LOG2E; kf.z *= LOG2E; kf.w *= LOG2E;
        u32 kh01, kl01, kh23, kl23;
        split16(kf.x, kf.y, kh01, kl01);
        split16(kf.z, kf.w, kh23, kl23);
        *(uint2*)(smc + (lreg - smb) + 0 * TILE + lrow * RS + d4 * 8) = make_uint2(kh01, kh23);
        *(uint2*)(smc + (lreg - smb) + 1 * TILE + lrow * RS + d4 * 8) = make_uint2(kl01, kl23);

        float4 vf = *(const float4*)(V + bh_off + (size_t)pos * DIM + d4 * 4);
        u32 vh01 = pkbf(vf.x, vf.y), vh23 = pkbf(vf.z, vf.w);
        u32 vl01 = pkbf(vf.x - lo_f(vh01), vf.y - hi_f(vh01));
        u32 vl23 = pkbf(vf.z - lo_f(vh23), vf.w - hi_f(vh23));
        *(uint2*)(smc + (lreg - smb) + 2 * TILE + lrow * RS + d4 * 8) = make_uint2(vh01, vh23);
        *(uint2*)(smc + (lreg - smb) + 3 * TILE + lrow * RS + d4 * 8) = make_uint2(vl01, vl23);
    }
    if (tid < 128)
        s_mask[tid] = (Mask[b * SEQ + qp * 128 + tid] == 0.0f) ? 0.0f : 1.0f;
    __syncthreads();

    // ---- persistent Q A-fragments (fp16 hi/lo) ----
    u32 qh[2][4][4], ql[2][4][4];
    {
        int r    = L & 7;
        int rofs = ((L >> 3) & 1) * 8;
        int cofs = ((L >> 4) & 1) * 16;
        #pragma unroll
        for (int m = 0; m < 2; m++)
            #pragma unroll
            for (int kt = 0; kt < 4; kt++) {
                u32 a = (qw + m * 16 + r + rofs) * RS + kt * 32 + cofs;
                ldsm4(qh[m][kt], QHs + a);
                ldsm4(ql[m][kt], QLs + a);
            }
    }
    __syncthreads();   // Q staging (R2) free

    const char* gsrc = (const char*)g_split + (size_t)bh * 4 * 32768;

    // issue g0 -> R2
    {
        #pragma unroll
        for (int t = 0; t < 4; t++)
            #pragma unroll
            for (int kk = 0; kk < 4; kk++) {
                int seg = tid + kk * NTHREADS;
                int row = seg >> 3, c16 = seg & 7;
                cpasync16(R2 + t * TILE + row * RS + c16 * 16,
                          gsrc + t * 32768 + row * 128 + c16 * 16);
            }
        if (tid < 64)
            s_mask[128 + tid] = (Mask[b * SEQ + gpos(tid)] == 0.0f) ? 0.0f : 1.0f;
        CP_COMMIT();
    }

    const int r    = L & 7;
    const u32 aQK  = (u32)(((r + ((L >> 4) & 1) * 8) * RS) + ((L >> 3) & 1) * 16);
    const u32 aPV  = (u32)(((r + ((L >> 3) & 1) * 8) * RS) + ((L >> 4) & 1) * 16);
    const int mcol = 2 * (L & 3);

    float OT[2][8][4];
    #pragma unroll
    for (int m = 0; m < 2; m++)
        #pragma unroll
        for (int nt = 0; nt < 8; nt++)
            #pragma unroll
            for (int e = 0; e < 4; e++) OT[m][nt][e] = 0.0f;
    float rs[2][2] = {{0.f, 0.f}, {0.f, 0.f}};

    u32 rbase = (warp < 2) ? R0 : R1;
    const float* mptr = s_mask + ((warp < 2) ? 0 : 64);

    #pragma unroll 1
    for (int c = 0; c < 5; c++) {
        if (c == 1) {
            __syncthreads();
            #pragma unroll
            for (int t = 0; t < 4; t++)              // g1 -> R0
                #pragma unroll
                for (int kk = 0; kk < 4; kk++) {
                    int seg = tid + kk * NTHREADS;
                    int row = seg >> 3, c16 = seg & 7;
                    cpasync16(R0 + t * TILE + row * RS + c16 * 16,
                              gsrc + t * 32768 + (64 + row) * 128 + c16 * 16);
                }
            if (tid < 64)
                s_mask[192 + tid] = (Mask[b * SEQ + gpos(64 + tid)] == 0.0f) ? 0.0f : 1.0f;
            CP_COMMIT();
            #pragma unroll
            for (int t = 0; t < 4; t++)              // g2 -> R1
                #pragma unroll
                for (int kk = 0; kk < 4; kk++) {
                    int seg = tid + kk * NTHREADS;
                    int row = seg >> 3, c16 = seg & 7;
                    cpasync16(R1 + t * TILE + row * RS + c16 * 16,
                              gsrc + t * 32768 + (128 + row) * 128 + c16 * 16);
                }
            if (tid < 64)
                s_mask[256 + tid] = (Mask[b * SEQ + gpos(128 + tid)] == 0.0f) ? 0.0f : 1.0f;
            CP_COMMIT();
            CP_WAIT(2);
            __syncthreads();
            rbase = R2; mptr = s_mask + 128;
        } else if (c == 2) {
            __syncthreads();
            #pragma unroll
            for (int t = 0; t < 4; t++)              // g3 -> R2
                #pragma unroll
                for (int kk = 0; kk < 4; kk++) {
                    int seg = tid + kk * NTHREADS;
                    int row = seg >> 3, c16 = seg & 7;
                    cpasync16(R2 + t * TILE + row * RS + c16 * 16,
                              gsrc + t * 32768 + (192 + row) * 128 + c16 * 16);
                }
            if (tid < 64)
                s_mask[320 + tid] = (Mask[b * SEQ + gpos(192 + tid)] == 0.0f) ? 0.0f : 1.0f;
            CP_COMMIT();
            CP_WAIT(2);
            __syncthreads();
            rbase = R0; mptr = s_mask + 192;
        } else if (c == 3) {
            CP_WAIT(1);
            __syncthreads();
            rbase = R1; mptr = s_mask + 256;
        } else if (c == 4) {
            CP_WAIT(0);
            __syncthreads();
            rbase = R2; mptr = s_mask + 320;
        }

        const u32 aKH = rbase, aKL = rbase + TILE;
        const u32 aVH = rbase + 2 * TILE, aVL = rbase + 3 * TILE;

        #pragma unroll
        for (int np = 0; np < 4; np++) {
            // ========= QK: main f32acc + shared f16acc correction chain =========
            float C[2][2][4];
            u32   D[2][2][2];
            #pragma unroll
            for (int m = 0; m < 2; m++)
                #pragma unroll
                for (int hh = 0; hh < 2; hh++) {
                    #pragma unroll
                    for (int e = 0; e < 4; e++) C[m][hh][e] = 0.0f;
                    D[m][hh][0] = 0u; D[m][hh][1] = 0u;
                }

            #pragma unroll
            for (int kt = 0; kt < 4; kt++) {
                u32 KH[4], KL[4];
                u32 a = aQK + (u32)(np * 16 * RS + kt * 32);
                ldsm4(KH, aKH + a);
                ldsm4(KL, aKL + a);
                // main: qh * KH -> f32
                mma_hf32(C[0][0], qh[0][kt], KH[0], KH[1]);
                mma_hf32(C[1][0], qh[1][kt], KH[0], KH[1]);
                mma_hf32(C[0][1], qh[0][kt], KH[2], KH[3]);
                mma_hf32(C[1][1], qh[1][kt], KH[2], KH[3]);
                // corrections: qh*KL + ql*KH -> shared f16 chain
                mma_hf16(D[0][0], qh[0][kt], KL[0], KL[1]);
                mma_hf16(D[1][0], qh[1][kt], KL[0], KL[1]);
                mma_hf16(D[0][1], qh[0][kt], KL[2], KL[3]);
                mma_hf16(D[1][1], qh[1][kt], KL[2], KL[3]);
                mma_hf16(D[0][0], ql[0][kt], KH[0], KH[1]);
                mma_hf16(D[1][0], ql[1][kt], KH[0], KH[1]);
                mma_hf16(D[0][1], ql[0][kt], KH[2], KH[3]);
                mma_hf16(D[1][1], ql[1][kt], KH[2], KH[3]);
            }

            // ========= epilogue: score = C + corr; p = ex2(score - SHIFT2)*mask =========
            u32 ph[2][4], pl[2][4];
            float2 mmE = *(const float2*)(mptr + (2 * np) * 8 + mcol);
            float2 mmO = *(const float2*)(mptr + (2 * np + 1) * 8 + mcol);
            #pragma unroll
            for (int m = 0; m < 2; m++) {
                float2 d0 = h2f2(D[m][0][0]);
                float2 d1 = h2f2(D[m][0][1]);
                float p0 = ex2(C[m][0][0] + d0.x - SHIFT2) * mmE.x;
                float p1 = ex2(C[m][0][1] + d0.y - SHIFT2) * mmE.y;
                float p2 = ex2(C[m][0][2] + d1.x - SHIFT2) * mmE.x;
                float p3 = ex2(C[m][0][3] + d1.y - SHIFT2) * mmE.y;
                rs[m][0] += p0 + p1;
                rs[m][1] += p2 + p3;
                u32 hA = pkbf(p0, p1), hB = pkbf(p2, p3);
                pl[m][0] = pkbf(p0 - lo_f(hA), p1 - hi_f(hA));
                pl[m][1] = pkbf(p2 - lo_f(hB), p3 - hi_f(hB));
                ph[m][0] = hA; ph[m][1] = hB;

                float2 e0 = h2f2(D[m][1][0]);
                float2 e1 = h2f2(D[m][1][1]);
                float q0 = ex2(C[m][1][0] + e0.x - SHIFT2) * mmO.x;
                float q1 = ex2(C[m][1][1] + e0.y - SHIFT2) * mmO.y;
                float q2 = ex2(C[m][1][2] + e1.x - SHIFT2) * mmO.x;
                float q3 = ex2(C[m][1][3] + e1.y - SHIFT2) * mmO.y;
                rs[m][0] += q0 + q1;
                rs[m][1] += q2 + q3;
                u32 hC = pkbf(q0, q1), hD = pkbf(q2, q3);
                pl[m][2] = pkbf(q0 - lo_f(hC), q1 - hi_f(hC));
                pl[m][3] = pkbf(q2 - lo_f(hD), q3 - hi_f(hD));
                ph[m][2] = hC; ph[m][3] = hD;
            }

            // ========= PV: bf16 3-term, dt-paired (unchanged) =========
            #pragma unroll
            for (int dt2 = 0; dt2 < 2; dt2++) {
                int dt0 = 2 * dt2, dt1 = 2 * dt2 + 1;
                int nt0 = 4 * dt2;
                u32 VH0[4], VL0[4], VH1[4], VL1[4];
                u32 o0 = aPV + (u32)(np * 16 * RS + dt0 * 32);
                u32 o1 = aPV + (u32)(np * 16 * RS + dt1 * 32);
                ldsm4t(VH0, aVH + o0);
                ldsm4t(VH1, aVH + o1);
                ldsm4t(VL0, aVL + o0);
                ldsm4t(VL1, aVL + o1);
                // Ph*Vh
                mma_bf(OT[0][nt0 + 0], ph[0], VH0[0], VH0[1]);
                mma_bf(OT[1][nt0 + 0], ph[1], VH0[0], VH0[1]);
                mma_bf(OT[0][nt0 + 1], ph[0], VH0[2], VH0[3]);
                mma_bf(OT[1][nt0 + 1], ph[1], VH0[2], VH0[3]);
                mma_bf(OT[0][nt0 + 2], ph[0], VH1[0], VH1[1]);
                mma_bf(OT[1][nt0 + 2], ph[1], VH1[0], VH1[1]);
                mma_bf(OT[0][nt0 + 3], ph[0], VH1[2], VH1[3]);
                mma_bf(OT[1][nt0 + 3], ph[1], VH1[2], VH1[3]);
                // Pl*Vh
                mma_bf(OT[0][nt0 + 0], pl[0], VH0[0], VH0[1]);
                mma_bf(OT[1][nt0 + 0], pl[1], VH0[0], VH0[1]);
                mma_bf(OT[0][nt0 + 1], pl[0], VH0[2], VH0[3]);
                mma_bf(OT[1][nt0 + 1], pl[1], VH0[2], VH0[3]);
                mma_bf(OT[0][nt0 + 2], pl[0], VH1[0], VH1[1]);
                mma_bf(OT[1][nt0 + 2], pl[1], VH1[0], VH1[1]);
                mma_bf(OT[0][nt0 + 3], pl[0], VH1[2], VH1[3]);
                mma_bf(OT[1][nt0 + 3], pl[1], VH1[2], VH1[3]);
                // Ph*Vl
                mma_bf(OT[0][nt0 + 0], ph[0], VL0[0], VL0[1]);
                mma_bf(OT[1][nt0 + 0], ph[1], VL0[0], VL0[1]);
                mma_bf(OT[0][nt0 + 1], ph[0], VL0[2], VL0[3]);
                mma_bf(OT[1][nt0 + 1], ph[1], VL0[2], VL0[3]);
                mma_bf(OT[0][nt0 + 2], ph[0], VL1[0], VL1[1]);
                mma_bf(OT[1][nt0 + 2], ph[1], VL1[0], VL1[1]);
                mma_bf(OT[0][nt0 + 3], ph[0], VL1[2], VL1[3]);
                mma_bf(OT[1][nt0 + 3], ph[1], VL1[2], VL1[3]);
            }
        }
    }

    // ---- reduce row sums, normalize, store ----
    #pragma unroll
    for (int m = 0; m < 2; m++)
        #pragma unroll
        for (int g = 0; g < 2; g++) {
            float s = rs[m][g];
            s += __shfl_xor_sync(0xffffffffu, s, 1);
            s += __shfl_xor_sync(0xffffffffu, s, 2);
            rs[m][g] = s;
        }

    #pragma unroll
    for (int m = 0; m < 2; m++) {
        float inv0 = 1.0f / rs[m][0];
        float inv1 = 1.0f / rs[m][1];
        int row0 = qw + m * 16 + (L >> 2);
        float* o0 = Out + q_off + (size_t)row0 * DIM + mcol;
        float* o1 = o0 + 8 * DIM;
        #pragma unroll
        for (int nt = 0; nt < 8; nt++) {
            *(float2*)(o0 + nt * 8) = make_float2(OT[m][nt][0] * inv0, OT[m][nt][1] * inv0);
            *(float2*)(o1 + nt * 8) = make_float2(OT[m][nt][2] * inv1, OT[m][nt][3] * inv1);
        }
    }
}

extern "C" void kernel_launch(void* const* d_in, const int* in_sizes, int n_in,
                              void* d_out, int out_size)
{
    const float* Q = (const float*)d_in[0];
    const float* K = (const float*)d_in[1];
    const float* V = (const float*)d_in[2];
    const float* M = (const float*)d_in[3];
    float* O = (float*)d_out;

    dim3 pgrid(16, 32);
    prepass_kernel<<<pgrid, 256>>>(K, V);

    cudaFuncSetAttribute(sparse_attn_mma,
                         cudaFuncAttributeMaxDynamicSharedMemorySize, SM_TOTAL);
    dim3 grid(SEQ / 128, HEADS, BSZ);   // (32, 16, 2)
    sparse_attn_mma<<<grid, NTHREADS, SM_TOTAL>>>(Q, K, V, M, O);
}

// round 17
// speedup vs baseline: 1.0235x; 1.0235x over previous
#include <cuda_runtime.h>
#include <cuda_bf16.h>
#include <cuda_fp16.h>

// SparseSelfAttention via portable mma.sync, FA2-style. R17:
// QK: fp16 main (f32acc) + fp16 corrections (shared f16acc chain) — as R16.
// PV: 2 terms (Ph*Vh + Ph*Vl), P in fp16 enabled by per-row running max
// (rescale O/rowsum by ex2(m_old-m_new) per 32-key block). V fp16 hi/lo.
// 320 MMAs/warp/chunk vs 384 in R16.

#define BSZ    2
#define HEADS  16
#define SEQ    4096
#define DIM    64
#define LOG2E  1.4426950408889634f
#define NTHREADS 128

#define RS 144                  // smem row stride in BYTES
#define TILE (64 * RS)          // 9216 B per 64-row 16-bit tile
#define REG  (4 * TILE)         // KH,KL,VH,VL region = 36864 B

#define SM_MASK  (3 * REG)                 // 110592
#define SM_TOTAL (SM_MASK + 6 * 64 * 4)    // 112128 B -> 2 CTAs/SM

typedef unsigned int u32;

// pre-pass scratch: [bh][KH,KL,VH,VL][256 g][64 d] fp16 = 4 MB (K pre-scaled by log2e)
__device__ __half g_split[32][4][256][64];

static __device__ __forceinline__ u32 smem_u32(const void* p) {
    u32 a;
    asm("{ .reg .u64 t; cvta.to.shared.u64 t, %1; cvt.u32.u64 %0, t; }" : "=r"(a) : "l"(p));
    return a;
}
// f16x2 {lo=a, hi=b}
static __device__ __forceinline__ u32 pkhf(float a, float b) {
    u32 r;
    asm("cvt.rn.f16x2.f32 %0, %1, %2;" : "=r"(r) : "f"(b), "f"(a));
    return r;
}
static __device__ __forceinline__ float2 h2f2(u32 p) {
    float lo, hi;
    asm("{ .reg .f16 a, b; mov.b32 {a, b}, %2; cvt.f32.f16 %0, a; cvt.f32.f16 %1, b; }"
        : "=f"(lo), "=f"(hi) : "r"(p));
    return make_float2(lo, hi);
}
// fp16 hi/lo split of a float pair
static __device__ __forceinline__ void split16(float a, float b, u32& h, u32& l) {
    h = pkhf(a, b);
    float2 hf = h2f2(h);
    l = pkhf(a - hf.x, b - hf.y);
}
static __device__ __forceinline__ float ex2(float x) {
    float y;
    asm("ex2.approx.f32 %0, %1;" : "=f"(y) : "f"(x));
    return y;
}
static __device__ __forceinline__ void ldsm4(u32* r, u32 a) {
    asm volatile("ldmatrix.sync.aligned.m8n8.x4.shared.b16 {%0,%1,%2,%3}, [%4];"
                 : "=r"(r[0]), "=r"(r[1]), "=r"(r[2]), "=r"(r[3]) : "r"(a));
}
static __device__ __forceinline__ void ldsm4t(u32* r, u32 a) {
    asm volatile("ldmatrix.sync.aligned.m8n8.x4.trans.shared.b16 {%0,%1,%2,%3}, [%4];"
                 : "=r"(r[0]), "=r"(r[1]), "=r"(r[2]), "=r"(r[3]) : "r"(a));
}
// fp16 inputs, f32 accum
static __device__ __forceinline__ void mma_hf32(float* c, const u32* a, u32 b0, u32 b1) {
    asm volatile(
        "mma.sync.aligned.m16n8k16.row.col.f32.f16.f16.f32 "
        "{%0,%1,%2,%3}, {%4,%5,%6,%7}, {%8,%9}, {%0,%1,%2,%3};"
        : "+f"(c[0]), "+f"(c[1]), "+f"(c[2]), "+f"(c[3])
        : "r"(a[0]), "r"(a[1]), "r"(a[2]), "r"(a[3]), "r"(b0), "r"(b1));
}
// fp16 inputs, f16 accum (corrections)
static __device__ __forceinline__ void mma_hf16(u32* c, const u32* a, u32 b0, u32 b1) {
    asm volatile(
        "mma.sync.aligned.m16n8k16.row.col.f16.f16.f16.f16 "
        "{%0,%1}, {%2,%3,%4,%5}, {%6,%7}, {%0,%1};"
        : "+r"(c[0]), "+r"(c[1])
        : "r"(a[0]), "r"(a[1]), "r"(a[2]), "r"(a[3]), "r"(b0), "r"(b1));
}
static __device__ __forceinline__ void cpasync16(u32 dst, const void* src) {
    asm volatile("cp.async.cg.shared.global [%0], [%1], 16;" :: "r"(dst), "l"(src));
}
#define CP_COMMIT() asm volatile("cp.async.commit_group;" ::: "memory")
#define CP_WAIT(n)  asm volatile("cp.async.wait_group %0;" :: "n"(n) : "memory")

static __device__ __forceinline__ int gpos(int g) {
    int blk = g >> 2, off = g & 3;
    return blk * 64 + (off == 0 ? 0 : 60 + off);
}

// ========== pre-pass: gather + fp16-split global K (x log2e) and V ==========
__global__ __launch_bounds__(256)
void prepass_kernel(const float* __restrict__ K, const float* __restrict__ V)
{
    const int bh  = blockIdx.y;
    const int idx = threadIdx.x + blockIdx.x * 256;    // 0..4095
    const size_t bh_off = (size_t)bh * SEQ * DIM;
    uint2* out = (uint2*)g_split;

    int g = idx >> 4, d4 = idx & 15;
    int pos = gpos(g);

    float4 kf = *(const float4*)(K + bh_off + (size_t)pos * DIM + d4 * 4);
    kf.x *= LOG2E; kf.y *= LOG2E; kf.z *= LOG2E; kf.w *= LOG2E;
    u32 h01, l01, h23, l23;
    split16(kf.x, kf.y, h01, l01);
    split16(kf.z, kf.w, h23, l23);
    out[(bh * 4 + 0) * 4096 + g * 16 + d4] = make_uint2(h01, h23);
    out[(bh * 4 + 1) * 4096 + g * 16 + d4] = make_uint2(l01, l23);

    float4 vf = *(const float4*)(V + bh_off + (size_t)pos * DIM + d4 * 4);
    u32 vh01, vl01, vh23, vl23;
    split16(vf.x, vf.y, vh01, vl01);
    split16(vf.z, vf.w, vh23, vl23);
    out[(bh * 4 + 2) * 4096 + g * 16 + d4] = make_uint2(vh01, vh23);
    out[(bh * 4 + 3) * 4096 + g * 16 + d4] = make_uint2(vl01, vl23);
}

// ================= main kernel =================
extern __shared__ char smc[];

__global__ __launch_bounds__(NTHREADS, 2)
void sparse_attn_mma(const float* __restrict__ Q,
                     const float* __restrict__ K,
                     const float* __restrict__ V,
                     const float* __restrict__ Mask,
                     float* __restrict__ Out)
{
    const int qp = blockIdx.x;
    const int h  = blockIdx.y;
    const int b  = blockIdx.z;
    const int bh = b * HEADS + h;
    const size_t bh_off = (size_t)bh * SEQ * DIM;
    const size_t q_off  = bh_off + (size_t)qp * 128 * DIM;

    const int tid  = threadIdx.x;
    const int L    = tid & 31;
    const int warp = tid >> 5;
    const int qw   = warp * 32;

    const u32 smb = smem_u32(smc);
    const u32 R0 = smb, R1 = smb + REG, R2 = smb + 2 * REG;
    float* s_mask = (float*)(smc + SM_MASK);
    const u32 QHs = R2;
    const u32 QLs = R2 + 2 * TILE;

    // ---- prologue: Q (fp16 split) -> R2, local K/V (fp16 split) -> R0/R1 ----
    #pragma unroll
    for (int i = 0; i < 16; i++) {
        int idx = tid + i * NTHREADS;
        int row = idx >> 4, d4 = idx & 15;
        u32 lreg = (row < 64) ? R0 : R1;
        int lrow = row & 63;

        float4 f = *(const float4*)(Q + q_off + (size_t)row * DIM + d4 * 4);
        u32 h01, l01, h23, l23;
        split16(f.x, f.y, h01, l01);
        split16(f.z, f.w, h23, l23);
        *(uint2*)(smc + (QHs - smb) + row * RS + d4 * 8) = make_uint2(h01, h23);
        *(uint2*)(smc + (QLs - smb) + row * RS + d4 * 8) = make_uint2(l01, l23);

        int pos = qp * 128 + row;
        float4 kf = *(const float4*)(K + bh_off + (size_t)pos * DIM + d4 * 4);
        kf.x *= LOG2E; kf.y *= LOG2E; kf.z *= LOG2E; kf.w *= LOG2E;
        u32 kh01, kl01, kh23, kl23;
        split16(kf.x, kf.y, kh01, kl01);
        split16(kf.z, kf.w, kh23, kl23);
        *(uint2*)(smc + (lreg - smb) + 0 * TILE + lrow * RS + d4 * 8) = make_uint2(kh01, kh23);
        *(uint2*)(smc + (lreg - smb) + 1 * TILE + lrow * RS + d4 * 8) = make_uint2(kl01, kl23);

        float4 vf = *(const float4*)(V + bh_off + (size_t)pos * DIM + d4 * 4);
        u32 vh01, vl01, vh23, vl23;
        split16(vf.x, vf.y, vh01, vl01);
        split16(vf.z, vf.w, vh23, vl23);
        *(uint2*)(smc + (lreg - smb) + 2 * TILE + lrow * RS + d4 * 8) = make_uint2(vh01, vh23);
        *(uint2*)(smc + (lreg - smb) + 3 * TILE + lrow * RS + d4 * 8) = make_uint2(vl01, vl23);
    }
    if (tid < 128)
        s_mask[tid] = (Mask[b * SEQ + qp * 128 + tid] == 0.0f) ? 0.0f : 1.0f;
    __syncthreads();

    // ---- persistent Q A-fragments (fp16 hi/lo) ----
    u32 qh[2][4][4], ql[2][4][4];
    {
        int r    = L & 7;
        int rofs = ((L >> 3) & 1) * 8;
        int cofs = ((L >> 4) & 1) * 16;
        #pragma unroll
        for (int m = 0; m < 2; m++)
            #pragma unroll
            for (int kt = 0; kt < 4; kt++) {
                u32 a = (qw + m * 16 + r + rofs) * RS + kt * 32 + cofs;
                ldsm4(qh[m][kt], QHs + a);
                ldsm4(ql[m][kt], QLs + a);
            }
    }
    __syncthreads();   // Q staging (R2) free

    const char* gsrc = (const char*)g_split + (size_t)bh * 4 * 32768;

    // issue g0 -> R2
    {
        #pragma unroll
        for (int t = 0; t < 4; t++)
            #pragma unroll
            for (int kk = 0; kk < 4; kk++) {
                int seg = tid + kk * NTHREADS;
                int row = seg >> 3, c16 = seg & 7;
                cpasync16(R2 + t * TILE + row * RS + c16 * 16,
                          gsrc + t * 32768 + row * 128 + c16 * 16);
            }
        if (tid < 64)
            s_mask[128 + tid] = (Mask[b * SEQ + gpos(tid)] == 0.0f) ? 0.0f : 1.0f;
        CP_COMMIT();
    }

    const int r    = L & 7;
    const u32 aQK  = (u32)(((r + ((L >> 4) & 1) * 8) * RS) + ((L >> 3) & 1) * 16);
    const u32 aPV  = (u32)(((r + ((L >> 3) & 1) * 8) * RS) + ((L >> 4) & 1) * 16);
    const int mcol = 2 * (L & 3);

    float OT[2][8][4];
    #pragma unroll
    for (int m = 0; m < 2; m++)
        #pragma unroll
        for (int nt = 0; nt < 8; nt++)
            #pragma unroll
            for (int e = 0; e < 4; e++) OT[m][nt][e] = 0.0f;
    float rs[2][2]   = {{0.f, 0.f}, {0.f, 0.f}};
    float mold[2][2] = {{-1e30f, -1e30f}, {-1e30f, -1e30f}};

    u32 rbase = (warp < 2) ? R0 : R1;
    const float* mptr = s_mask + ((warp < 2) ? 0 : 64);

    #pragma unroll 1
    for (int c = 0; c < 5; c++) {
        if (c == 1) {
            __syncthreads();
            #pragma unroll
            for (int t = 0; t < 4; t++)              // g1 -> R0
                #pragma unroll
                for (int kk = 0; kk < 4; kk++) {
                    int seg = tid + kk * NTHREADS;
                    int row = seg >> 3, c16 = seg & 7;
                    cpasync16(R0 + t * TILE + row * RS + c16 * 16,
                              gsrc + t * 32768 + (64 + row) * 128 + c16 * 16);
                }
            if (tid < 64)
                s_mask[192 + tid] = (Mask[b * SEQ + gpos(64 + tid)] == 0.0f) ? 0.0f : 1.0f;
            CP_COMMIT();
            #pragma unroll
            for (int t = 0; t < 4; t++)              // g2 -> R1
                #pragma unroll
                for (int kk = 0; kk < 4; kk++) {
                    int seg = tid + kk * NTHREADS;
                    int row = seg >> 3, c16 = seg & 7;
                    cpasync16(R1 + t * TILE + row * RS + c16 * 16,
                              gsrc + t * 32768 + (128 + row) * 128 + c16 * 16);
                }
            if (tid < 64)
                s_mask[256 + tid] = (Mask[b * SEQ + gpos(128 + tid)] == 0.0f) ? 0.0f : 1.0f;
            CP_COMMIT();
            CP_WAIT(2);
            __syncthreads();
            rbase = R2; mptr = s_mask + 128;
        } else if (c == 2) {
            __syncthreads();
            #pragma unroll
            for (int t = 0; t < 4; t++)              // g3 -> R2
                #pragma unroll
                for (int kk = 0; kk < 4; kk++) {
                    int seg = tid + kk * NTHREADS;
                    int row = seg >> 3, c16 = seg & 7;
                    cpasync16(R2 + t * TILE + row * RS + c16 * 16,
                              gsrc + t * 32768 + (192 + row) * 128 + c16 * 16);
                }
            if (tid < 64)
                s_mask[320 + tid] = (Mask[b * SEQ + gpos(192 + tid)] == 0.0f) ? 0.0f : 1.0f;
            CP_COMMIT();
            CP_WAIT(2);
            __syncthreads();
            rbase = R0; mptr = s_mask + 192;
        } else if (c == 3) {
            CP_WAIT(1);
            __syncthreads();
            rbase = R1; mptr = s_mask + 256;
        } else if (c == 4) {
            CP_WAIT(0);
            __syncthreads();
            rbase = R2; mptr = s_mask + 320;
        }

        const u32 aKH = rbase, aKL = rbase + TILE;
        const u32 aVH = rbase + 2 * TILE, aVL = rbase + 3 * TILE;

        #pragma unroll
        for (int np2 = 0; np2 < 2; np2++) {
            // ======== QK for np-pair: scores into Cs (mask-selected) ========
            float Cs[2][2][2][4];      // [nLocal][m][hh][e]
            #pragma unroll
            for (int n = 0; n < 2; n++) {
                const int np = 2 * np2 + n;
                float C[2][2][4];
                u32   D[2][2][2];
                #pragma unroll
                for (int m = 0; m < 2; m++)
                    #pragma unroll
                    for (int hh = 0; hh < 2; hh++) {
                        #pragma unroll
                        for (int e = 0; e < 4; e++) C[m][hh][e] = 0.0f;
                        D[m][hh][0] = 0u; D[m][hh][1] = 0u;
                    }
                #pragma unroll
                for (int kt = 0; kt < 4; kt++) {
                    u32 KH[4], KL[4];
                    u32 a = aQK + (u32)(np * 16 * RS + kt * 32);
                    ldsm4(KH, aKH + a);
                    ldsm4(KL, aKL + a);
                    mma_hf32(C[0][0], qh[0][kt], KH[0], KH[1]);
                    mma_hf32(C[1][0], qh[1][kt], KH[0], KH[1]);
                    mma_hf32(C[0][1], qh[0][kt], KH[2], KH[3]);
                    mma_hf32(C[1][1], qh[1][kt], KH[2], KH[3]);
                    mma_hf16(D[0][0], qh[0][kt], KL[0], KL[1]);
                    mma_hf16(D[1][0], qh[1][kt], KL[0], KL[1]);
                    mma_hf16(D[0][1], qh[0][kt], KL[2], KL[3]);
                    mma_hf16(D[1][1], qh[1][kt], KL[2], KL[3]);
                    mma_hf16(D[0][0], ql[0][kt], KH[0], KH[1]);
                    mma_hf16(D[1][0], ql[1][kt], KH[0], KH[1]);
                    mma_hf16(D[0][1], ql[0][kt], KH[2], KH[3]);
                    mma_hf16(D[1][1], ql[1][kt], KH[2], KH[3]);
                }
                float2 mmE = *(const float2*)(mptr + (2 * np) * 8 + mcol);
                float2 mmO = *(const float2*)(mptr + (2 * np + 1) * 8 + mcol);
                #pragma unroll
                for (int m = 0; m < 2; m++) {
                    float2 d0 = h2f2(D[m][0][0]);
                    float2 d1 = h2f2(D[m][0][1]);
                    Cs[n][m][0][0] = (mmE.x > 0.5f) ? (C[m][0][0] + d0.x) : -60000.0f;
                    Cs[n][m][0][1] = (mmE.y > 0.5f) ? (C[m][0][1] + d0.y) : -60000.0f;
                    Cs[n][m][0][2] = (mmE.x > 0.5f) ? (C[m][0][2] + d1.x) : -60000.0f;
                    Cs[n][m][0][3] = (mmE.y > 0.5f) ? (C[m][0][3] + d1.y) : -60000.0f;
                    float2 e0 = h2f2(D[m][1][0]);
                    float2 e1 = h2f2(D[m][1][1]);
                    Cs[n][m][1][0] = (mmO.x > 0.5f) ? (C[m][1][0] + e0.x) : -60000.0f;
                    Cs[n][m][1][1] = (mmO.y > 0.5f) ? (C[m][1][1] + e0.y) : -60000.0f;
                    Cs[n][m][1][2] = (mmO.x > 0.5f) ? (C[m][1][2] + e1.x) : -60000.0f;
                    Cs[n][m][1][3] = (mmO.y > 0.5f) ? (C[m][1][3] + e1.y) : -60000.0f;
                }
            }

            // ======== running max + rescale (per 32-key block) ========
            {
                float ml[2][2] = {{-1e30f, -1e30f}, {-1e30f, -1e30f}};
                #pragma unroll
                for (int n = 0; n < 2; n++)
                    #pragma unroll
                    for (int m = 0; m < 2; m++)
                        #pragma unroll
                        for (int hh = 0; hh < 2; hh++) {
                            ml[m][0] = fmaxf(ml[m][0], fmaxf(Cs[n][m][hh][0], Cs[n][m][hh][1]));
                            ml[m][1] = fmaxf(ml[m][1], fmaxf(Cs[n][m][hh][2], Cs[n][m][hh][3]));
                        }
                #pragma unroll
                for (int m = 0; m < 2; m++)
                    #pragma unroll
                    for (int g = 0; g < 2; g++) {
                        float v = ml[m][g];
                        v = fmaxf(v, __shfl_xor_sync(0xffffffffu, v, 1));
                        v = fmaxf(v, __shfl_xor_sync(0xffffffffu, v, 2));
                        float mn = fmaxf(mold[m][g], v);
                        float sc = ex2(mold[m][g] - mn);
                        rs[m][g] *= sc;
                        mold[m][g] = mn;
                        #pragma unroll
                        for (int nt = 0; nt < 8; nt++) {
                            OT[m][nt][2 * g]     *= sc;
                            OT[m][nt][2 * g + 1] *= sc;
                        }
                    }
            }

            // ======== exp -> fp16 P, then 2-term PV ========
            #pragma unroll
            for (int n = 0; n < 2; n++) {
                const int np = 2 * np2 + n;
                u32 ph[2][4];
                float2 mmE = *(const float2*)(mptr + (2 * np) * 8 + mcol);
                float2 mmO = *(const float2*)(mptr + (2 * np + 1) * 8 + mcol);
                #pragma unroll
                for (int m = 0; m < 2; m++) {
                    float p0 = ex2(Cs[n][m][0][0] - mold[m][0]) * mmE.x;
                    float p1 = ex2(Cs[n][m][0][1] - mold[m][0]) * mmE.y;
                    float p2 = ex2(Cs[n][m][0][2] - mold[m][1]) * mmE.x;
                    float p3 = ex2(Cs[n][m][0][3] - mold[m][1]) * mmE.y;
                    rs[m][0] += p0 + p1;
                    rs[m][1] += p2 + p3;
                    ph[m][0] = pkhf(p0, p1);
                    ph[m][1] = pkhf(p2, p3);
                    float q0 = ex2(Cs[n][m][1][0] - mold[m][0]) * mmO.x;
                    float q1 = ex2(Cs[n][m][1][1] - mold[m][0]) * mmO.y;
                    float q2 = ex2(Cs[n][m][1][2] - mold[m][1]) * mmO.x;
                    float q3 = ex2(Cs[n][m][1][3] - mold[m][1]) * mmO.y;
                    rs[m][0] += q0 + q1;
                    rs[m][1] += q2 + q3;
                    ph[m][2] = pkhf(q0, q1);
                    ph[m][3] = pkhf(q2, q3);
                }
                #pragma unroll
                for (int dt2 = 0; dt2 < 2; dt2++) {
                    int dt0 = 2 * dt2, dt1 = 2 * dt2 + 1;
                    int nt0 = 4 * dt2;
                    u32 VH0[4], VH1[4], VL0[4], VL1[4];
                    u32 o0 = aPV + (u32)(np * 16 * RS + dt0 * 32);
                    u32 o1 = aPV + (u32)(np * 16 * RS + dt1 * 32);
                    ldsm4t(VH0, aVH + o0);
                    ldsm4t(VH1, aVH + o1);
                    ldsm4t(VL0, aVL + o0);
                    ldsm4t(VL1, aVL + o1);
                    // Ph*Vh
                    mma_hf32(OT[0][nt0 + 0], ph[0], VH0[0], VH0[1]);
                    mma_hf32(OT[1][nt0 + 0], ph[1], VH0[0], VH0[1]);
                    mma_hf32(OT[0][nt0 + 1], ph[0], VH0[2], VH0[3]);
                    mma_hf32(OT[1][nt0 + 1], ph[1], VH0[2], VH0[3]);
                    mma_hf32(OT[0][nt0 + 2], ph[0], VH1[0], VH1[1]);
                    mma_hf32(OT[1][nt0 + 2], ph[1], VH1[0], VH1[1]);
                    mma_hf32(OT[0][nt0 + 3], ph[0], VH1[2], VH1[3]);
                    mma_hf32(OT[1][nt0 + 3], ph[1], VH1[2], VH1[3]);
                    // Ph*Vl
                    mma_hf32(OT[0][nt0 + 0], ph[0], VL0[0], VL0[1]);
                    mma_hf32(OT[1][nt0 + 0], ph[1], VL0[0], VL0[1]);
                    mma_hf32(OT[0][nt0 + 1], ph[0], VL0[2], VL0[3]);
                    mma_hf32(OT[1][nt0 + 1], ph[1], VL0[2], VL0[3]);
                    mma_hf32(OT[0][nt0 + 2], ph[0], VL1[0], VL1[1]);
                    mma_hf32(OT[1][nt0 + 2], ph[1], VL1[0], VL1[1]);
                    mma_hf32(OT[0][nt0 + 3], ph[0], VL1[2], VL1[3]);
                    mma_hf32(OT[1][nt0 + 3], ph[1], VL1[2], VL1[3]);
                }
            }
        }
    }

    // ---- reduce row sums, normalize, store ----
    #pragma unroll
    for (int m = 0; m < 2; m++)
        #pragma unroll
        for (int g = 0; g < 2; g++) {
            float s = rs[m][g];
            s += __shfl_xor_sync(0xffffffffu, s, 1);
            s += __shfl_xor_sync(0xffffffffu, s, 2);
            rs[m][g] = s;
        }

    #pragma unroll
    for (int m = 0; m < 2; m++) {
        float inv0 = 1.0f / rs[m][0];
        float inv1 = 1.0f / rs[m][1];
        int row0 = qw + m * 16 + (L >> 2);
        float* o0 = Out + q_off + (size_t)row0 * DIM + mcol;
        float* o1 = o0 + 8 * DIM;
        #pragma unroll
        for (int nt = 0; nt < 8; nt++) {
            *(float2*)(o0 + nt * 8) = make_float2(OT[m][nt][0] * inv0, OT[m][nt][1] * inv0);
            *(float2*)(o1 + nt * 8) = make_float2(OT[m][nt][2] * inv1, OT[m][nt][3] * inv1);
        }
    }
}

extern "C" void kernel_launch(void* const* d_in, const int* in_sizes, int n_in,
                              void* d_out, int out_size)
{
    const float* Q = (const float*)d_in[0];
    const float* K = (const float*)d_in[1];
    const float* V = (const float*)d_in[2];
    const float* M = (const float*)d_in[3];
    float* O = (float*)d_out;

    dim3 pgrid(16, 32);
    prepass_kernel<<<pgrid, 256>>>(K, V);

    cudaFuncSetAttribute(sparse_attn_mma,
                         cudaFuncAttributeMaxDynamicSharedMemorySize, SM_TOTAL);
    dim3 grid(SEQ / 128, HEADS, BSZ);   // (32, 16, 2)
    sparse_attn_mma<<<grid, NTHREADS, SM_TOTAL>>>(Q, K, V, M, O);
}